// round 1
// baseline (speedup 1.0000x reference)
#include <cuda_runtime.h>
#include <cstdint>

// Problem constants (fixed by the dataset)
#define N_NODES 500000
#define N_EDGES 2000000
#define C       32
#define NGRAPH  1024
#define HIDDEN  1024
#define LAYERS  8

// ---------------- scratch (device globals; no runtime allocation) ------------
__device__ float d_x   [(size_t)N_NODES * C];   // node features (updated in place)
__device__ float d_aggF[(size_t)N_NODES * C];   // forward aggregation buffer
__device__ float d_aggB[(size_t)N_NODES * C];   // backward aggregation buffer
__device__ float d_nF  [N_NODES];               // 1/(1+in-degree)
__device__ float d_nB  [N_NODES];               // 1/(1+out-degree)
__device__ float d_gsum[NGRAPH * C];            // per-graph feature sums
__device__ float d_gcnt[NGRAPH];                // per-graph node counts

// ---------------- init: x = emb[nodes], agg = 0 ------------------------------
__global__ void k_init_x(const int* __restrict__ nodes,
                         const float* __restrict__ emb, int n)
{
    long long idx = (long long)blockIdx.x * blockDim.x + threadIdx.x;
    if (idx >= (long long)n * C) return;
    int node = (int)(idx >> 5);
    int c    = (int)(idx & 31);
    int t    = __ldg(nodes + node);          // broadcast within warp
    d_x[idx]    = __ldg(emb + t * C + c);
    d_aggF[idx] = 0.f;
    d_aggB[idx] = 0.f;
}

// zero the small buffers
__global__ void k_zero_small(int n)
{
    int i = blockIdx.x * blockDim.x + threadIdx.x;
    if (i < n)          { d_nF[i] = 0.f; d_nB[i] = 0.f; }
    if (i < NGRAPH * C)   d_gsum[i] = 0.f;
    if (i < NGRAPH)       d_gcnt[i] = 0.f;
}

// degrees via atomics (cheap, once per launch)
__global__ void k_degrees(const int* __restrict__ src,
                          const int* __restrict__ dst, int E)
{
    int e = blockIdx.x * blockDim.x + threadIdx.x;
    if (e >= E) return;
    atomicAdd(&d_nF[__ldg(dst + e)], 1.f);   // in-degree  (targets)
    atomicAdd(&d_nB[__ldg(src + e)], 1.f);   // out-degree (sources)
}

__global__ void k_norm_finalize(int n)
{
    int i = blockIdx.x * blockDim.x + threadIdx.x;
    if (i >= n) return;
    d_nF[i] = 1.f / (1.f + d_nF[i]);
    d_nB[i] = 1.f / (1.f + d_nB[i]);
}

// ---------------- edge scatter: agg[dst] += x[src] ---------------------------
// 8 threads per edge, float4 lanes; vector reduction keeps L2 atomic op count low.
__global__ void k_edge_scatter(const int* __restrict__ src,
                               const int* __restrict__ dst,
                               int E, int toB)
{
    int idx = blockIdx.x * blockDim.x + threadIdx.x;
    int e   = idx >> 3;
    if (e >= E) return;
    int vi = idx & 7;

    int s = __ldg(src + e);                  // 8 lanes share -> 1 sector
    int t = __ldg(dst + e);

    const float4* x4 = reinterpret_cast<const float4*>(d_x);
    float4 v = __ldg(x4 + (size_t)s * 8 + vi);

    float* agg = toB ? d_aggB : d_aggF;
    float4* p  = reinterpret_cast<float4*>(agg) + (size_t)t * 8 + vi;
    asm volatile("red.global.add.v4.f32 [%0], {%1,%2,%3,%4};"
                 :: "l"(p), "f"(v.x), "f"(v.y), "f"(v.z), "f"(v.w)
                 : "memory");
}

// ---------------- node update: x += relu(hf@w0) + relu(hb@w1) ----------------
// 256 threads = 32 nodes/block, 1 thread = (node, 4 output channels).
// Also zeroes agg buffers for the next layer.
__global__ void k_node_update(const float* __restrict__ conv_w_l, int n)
{
    __shared__ float sw[2 * C * C];          // w0 then w1 (8 KB)
    __shared__ float sh[2 * 32 * 33];        // hf,hb staged per node, pad 33

    for (int i = threadIdx.x; i < 2 * C * C; i += blockDim.x)
        sw[i] = __ldg(conv_w_l + i);

    int nl = threadIdx.x >> 3;               // node within block 0..31
    int q  = threadIdx.x & 7;                // channel quad 0..7
    int node = blockIdx.x * 32 + nl;         // n divisible by 32 -> always valid

    float4* X4 = reinterpret_cast<float4*>(d_x);
    float4* F4 = reinterpret_cast<float4*>(d_aggF);
    float4* B4 = reinterpret_cast<float4*>(d_aggB);
    size_t i4 = (size_t)node * 8 + q;

    float4 xv = X4[i4];
    float4 af = F4[i4];  F4[i4] = make_float4(0.f, 0.f, 0.f, 0.f);
    float4 ab = B4[i4];  B4[i4] = make_float4(0.f, 0.f, 0.f, 0.f);
    float nf = d_nF[node];
    float nb = d_nB[node];

    float* shf = sh;
    float* shb = sh + 32 * 33;
    int so = nl * 33 + q * 4;
    shf[so + 0] = nf * (xv.x + af.x);
    shf[so + 1] = nf * (xv.y + af.y);
    shf[so + 2] = nf * (xv.z + af.z);
    shf[so + 3] = nf * (xv.w + af.w);
    shb[so + 0] = nb * (xv.x + ab.x);
    shb[so + 1] = nb * (xv.y + ab.y);
    shb[so + 2] = nb * (xv.z + ab.z);
    shb[so + 3] = nb * (xv.w + ab.w);
    __syncthreads();

    const float4* w0 = reinterpret_cast<const float4*>(sw);          // [32][8]
    const float4* w1 = reinterpret_cast<const float4*>(sw + C * C);

    float4 a0 = make_float4(0.f, 0.f, 0.f, 0.f);
    float4 a1 = make_float4(0.f, 0.f, 0.f, 0.f);
    #pragma unroll
    for (int k = 0; k < C; k++) {
        float hfk = shf[nl * 33 + k];
        float hbk = shb[nl * 33 + k];
        float4 wk0 = w0[k * 8 + q];
        float4 wk1 = w1[k * 8 + q];
        a0.x = fmaf(hfk, wk0.x, a0.x); a0.y = fmaf(hfk, wk0.y, a0.y);
        a0.z = fmaf(hfk, wk0.z, a0.z); a0.w = fmaf(hfk, wk0.w, a0.w);
        a1.x = fmaf(hbk, wk1.x, a1.x); a1.y = fmaf(hbk, wk1.y, a1.y);
        a1.z = fmaf(hbk, wk1.z, a1.z); a1.w = fmaf(hbk, wk1.w, a1.w);
    }

    float4 r;
    r.x = xv.x + fmaxf(a0.x, 0.f) + fmaxf(a1.x, 0.f);
    r.y = xv.y + fmaxf(a0.y, 0.f) + fmaxf(a1.y, 0.f);
    r.z = xv.z + fmaxf(a0.z, 0.f) + fmaxf(a1.z, 0.f);
    r.w = xv.w + fmaxf(a0.w, 0.f) + fmaxf(a1.w, 0.f);
    X4[i4] = r;
}

// ---------------- pooling: per-graph sum + count (batch is sorted) -----------
__global__ void k_pool(const int* __restrict__ batch, int n)
{
    int lane = threadIdx.x & 31;
    int warp = threadIdx.x >> 5;
    int base = blockIdx.x * 256 + warp * 32;   // first node of this warp

    float acc = 0.f;
    int cur = -1, run = 0;
    for (int j = 0; j < 32; j++) {
        int node = base + j;
        if (node >= n) break;
        int b = __ldg(batch + node);            // warp-uniform -> 1 sector
        float v = d_x[(size_t)node * C + lane];
        if (b != cur) {
            if (cur >= 0) {
                atomicAdd(&d_gsum[cur * C + lane], acc);
                if (lane == 0) atomicAdd(&d_gcnt[cur], (float)run);
            }
            cur = b; acc = 0.f; run = 0;
        }
        acc += v; run++;
    }
    if (cur >= 0) {
        atomicAdd(&d_gsum[cur * C + lane], acc);
        if (lane == 0) atomicAdd(&d_gcnt[cur], (float)run);
    }
}

// ---------------- MLP head: out[b] = relu(g@hw + hb) @ ow --------------------
__global__ void k_mlp(const float* __restrict__ hw,
                      const float* __restrict__ hb,
                      const float* __restrict__ ow,
                      float* __restrict__ out)
{
    int b = blockIdx.x;
    __shared__ float gs[C];
    __shared__ float red[8];
    if (threadIdx.x < C)
        gs[threadIdx.x] = d_gsum[b * C + threadIdx.x] / d_gcnt[b];
    __syncthreads();

    float part = 0.f;
    for (int j = threadIdx.x; j < HIDDEN; j += 256) {
        float h = __ldg(hb + j);
        #pragma unroll
        for (int k = 0; k < C; k++)
            h = fmaf(gs[k], __ldg(hw + k * HIDDEN + j), h);
        part += fmaxf(h, 0.f) * __ldg(ow + j);
    }
    #pragma unroll
    for (int off = 16; off > 0; off >>= 1)
        part += __shfl_down_sync(0xffffffffu, part, off);
    if ((threadIdx.x & 31) == 0) red[threadIdx.x >> 5] = part;
    __syncthreads();
    if (threadIdx.x == 0) {
        float s = 0.f;
        #pragma unroll
        for (int i = 0; i < 8; i++) s += red[i];
        out[b] = s;
    }
}

// ---------------- launch ------------------------------------------------------
extern "C" void kernel_launch(void* const* d_in, const int* in_sizes, int n_in,
                              void* d_out, int out_size)
{
    const int*   nodes    = (const int*)  d_in[0];
    const int*   sources  = (const int*)  d_in[1];
    const int*   targets  = (const int*)  d_in[2];
    const int*   batch    = (const int*)  d_in[3];
    const float* emb      = (const float*)d_in[4];
    const float* conv_w   = (const float*)d_in[5];
    const float* hidden_w = (const float*)d_in[6];
    const float* hidden_b = (const float*)d_in[7];
    const float* out_w    = (const float*)d_in[8];
    float*       out      = (float*)d_out;

    const int N = in_sizes[0];
    const int E = in_sizes[1];

    // init
    {
        long long tot = (long long)N * C;
        int blocks = (int)((tot + 255) / 256);
        k_init_x<<<blocks, 256>>>(nodes, emb, N);
        k_zero_small<<<(N + 255) / 256, 256>>>(N);
        k_degrees<<<(E + 255) / 256, 256>>>(sources, targets, E);
        k_norm_finalize<<<(N + 255) / 256, 256>>>(N);
    }

    // layers
    const int eb = (E * 8 + 255) / 256;       // 8 threads per edge
    const int nb = N / 32;                    // 500000 / 32 = 15625 exact
    for (int l = 0; l < LAYERS; l++) {
        k_edge_scatter<<<eb, 256>>>(sources, targets, E, 0);  // aggF[t] += x[s]
        k_edge_scatter<<<eb, 256>>>(targets, sources, E, 1);  // aggB[s] += x[t]
        k_node_update<<<nb, 256>>>(conv_w + (size_t)l * 2 * C * C, N);
    }

    // pooling + head
    k_pool<<<(N + 255) / 256, 256>>>(batch, N);
    k_mlp<<<NGRAPH, 256>>>(hidden_w, hidden_b, out_w, out);
}

// round 3
// speedup vs baseline: 1.9235x; 1.9235x over previous
#include <cuda_runtime.h>
#include <cstdint>

#define N_NODES 500000
#define N_EDGES 2000000
#define C       32
#define NGRAPH  1024
#define HIDDEN  1024
#define LAYERS  8

#define SCAN_BLK 256
#define ITEMS    8
#define CHUNK    (SCAN_BLK * ITEMS)                       // 2048
#define NBLK     ((N_NODES + CHUNK - 1) / CHUNK)          // 245

// ---------------- device scratch (static; no runtime allocation) -------------
__device__ float d_xa  [(size_t)N_NODES * C];             // feature ping
__device__ float d_xb  [(size_t)N_NODES * C];             // feature pong
__device__ int   d_cnt [2][N_NODES];                      // [0]=in-deg, [1]=out-deg
__device__ int   d_off [2][N_NODES + 1];                  // CSR row offsets
__device__ int   d_cur [2][N_NODES];                      // scatter cursors
__device__ int   d_csr [2][N_EDGES];                      // [0]: srcs by target, [1]: tgts by source
__device__ float d_norm[2][N_NODES];                      // 1/(1+deg)
__device__ int   d_bsum[2][NBLK];                         // scan block sums
__device__ float d_gsum[NGRAPH * C];
__device__ float d_gcnt[NGRAPH];

// ---------------- zero counters / pooling buffers ----------------------------
__global__ void k_zero()
{
    int i = blockIdx.x * blockDim.x + threadIdx.x;
    int stride = gridDim.x * blockDim.x;
    for (int j = i; j < N_NODES; j += stride) { d_cnt[0][j] = 0; d_cnt[1][j] = 0; }
    if (i < NGRAPH * C) d_gsum[i] = 0.f;
    if (i < NGRAPH)     d_gcnt[i] = 0.f;
}

// ---------------- degree histogram -------------------------------------------
__global__ void k_hist(const int* __restrict__ src, const int* __restrict__ dst, int E)
{
    int e = blockIdx.x * blockDim.x + threadIdx.x;
    if (e >= E) return;
    atomicAdd(&d_cnt[0][__ldg(dst + e)], 1);   // in-degree (by target)
    atomicAdd(&d_cnt[1][__ldg(src + e)], 1);   // out-degree (by source)
}

// ---------------- scan phase A: per-block sums --------------------------------
__global__ void k_scanA()
{
    int y = blockIdx.y;
    int base = blockIdx.x * CHUNK + threadIdx.x * ITEMS;
    int s = 0;
    #pragma unroll
    for (int j = 0; j < ITEMS; j++) {
        int i = base + j;
        if (i < N_NODES) s += d_cnt[y][i];
    }
    #pragma unroll
    for (int o = 16; o > 0; o >>= 1) s += __shfl_down_sync(0xffffffffu, s, o);
    __shared__ int sh[8];
    if ((threadIdx.x & 31) == 0) sh[threadIdx.x >> 5] = s;
    __syncthreads();
    if (threadIdx.x == 0) {
        int t = 0;
        #pragma unroll
        for (int w = 0; w < 8; w++) t += sh[w];
        d_bsum[y][blockIdx.x] = t;
    }
}

// ---------------- scan phase B: exclusive scan of block sums ------------------
__global__ void k_scanB(int E)
{
    int y = blockIdx.y;
    int tid = threadIdx.x;
    int lane = tid & 31, warp = tid >> 5;
    int val = (tid < NBLK) ? d_bsum[y][tid] : 0;
    int incl = val;
    #pragma unroll
    for (int o = 1; o < 32; o <<= 1) {
        int t = __shfl_up_sync(0xffffffffu, incl, o);
        if (lane >= o) incl += t;
    }
    __shared__ int shw[8];
    if (lane == 31) shw[warp] = incl;
    __syncthreads();
    if (warp == 0 && lane < 8) {
        int b = shw[lane], ib = b;
        #pragma unroll
        for (int o = 1; o < 8; o <<= 1) {
            int t = __shfl_up_sync(0xffu, ib, o);
            if (lane >= o) ib += t;
        }
        shw[lane] = ib - b;                     // exclusive warp base
    }
    __syncthreads();
    if (tid < NBLK) d_bsum[y][tid] = shw[warp] + incl - val;
    if (tid == 0) d_off[y][N_NODES] = E;
}

// ---------------- scan phase C: write offsets / cursors / norms ---------------
__global__ void k_scanC()
{
    int y = blockIdx.y;
    int lane = threadIdx.x & 31, warp = threadIdx.x >> 5;
    int base = blockIdx.x * CHUNK + threadIdx.x * ITEMS;

    int v[ITEMS]; int tsum = 0;
    #pragma unroll
    for (int j = 0; j < ITEMS; j++) {
        int i = base + j;
        v[j] = (i < N_NODES) ? d_cnt[y][i] : 0;
        tsum += v[j];
    }
    int incl = tsum;
    #pragma unroll
    for (int o = 1; o < 32; o <<= 1) {
        int t = __shfl_up_sync(0xffffffffu, incl, o);
        if (lane >= o) incl += t;
    }
    __shared__ int shw[8];
    if (lane == 31) shw[warp] = incl;
    __syncthreads();
    if (warp == 0 && lane < 8) {
        int b = shw[lane], ib = b;
        #pragma unroll
        for (int o = 1; o < 8; o <<= 1) {
            int t = __shfl_up_sync(0xffu, ib, o);
            if (lane >= o) ib += t;
        }
        shw[lane] = ib - b;
    }
    __syncthreads();
    int run = d_bsum[y][blockIdx.x] + shw[warp] + (incl - tsum);
    #pragma unroll
    for (int j = 0; j < ITEMS; j++) {
        int i = base + j;
        if (i < N_NODES) {
            d_off[y][i]  = run;
            d_cur[y][i]  = run;
            d_norm[y][i] = 1.f / (1.f + (float)v[j]);
            run += v[j];
        }
    }
}

// ---------------- CSR fill ----------------------------------------------------
__global__ void k_scatter(const int* __restrict__ src, const int* __restrict__ dst, int E)
{
    int e = blockIdx.x * blockDim.x + threadIdx.x;
    if (e >= E) return;
    int s = __ldg(src + e);
    int t = __ldg(dst + e);
    int p = atomicAdd(&d_cur[0][t], 1);  d_csr[0][p] = s;   // in-neighbors of t
    int q = atomicAdd(&d_cur[1][s], 1);  d_csr[1][q] = t;   // out-neighbors of s
}

// ---------------- init: x = emb[nodes] ----------------------------------------
__global__ void k_init_x(const int* __restrict__ nodes, const float* __restrict__ emb, int n)
{
    long long idx = (long long)blockIdx.x * blockDim.x + threadIdx.x;
    if (idx >= (long long)n * C) return;
    int node = (int)(idx >> 5);
    int c    = (int)(idx & 31);
    int t    = __ldg(nodes + node);
    d_xa[idx] = __ldg(emb + t * C + c);
}

// ---------------- fused layer: gather + norm + 2x GEMV + residual --------------
// warp per node: lane = channel
__global__ void __launch_bounds__(256) k_layer(const float* __restrict__ xin,
                                               float* __restrict__ xout,
                                               const float* __restrict__ w, int n)
{
    __shared__ float sw[2 * C * C];              // 8 KB weights
    __shared__ float shf[8][C];
    __shared__ float shb[8][C];

    for (int i = threadIdx.x; i < 2 * C * C; i += 256)
        sw[i] = __ldg(w + i);
    __syncthreads();

    int warp = threadIdx.x >> 5;
    int lane = threadIdx.x & 31;
    int node = blockIdx.x * 8 + warp;
    float xv = 0.f;

    if (node < n) {
        xv = xin[(size_t)node * C + lane];

        // forward: sum x over in-neighbors
        int b0 = __ldg(&d_off[0][node]), e0 = __ldg(&d_off[0][node + 1]);
        float hf = xv;
        int e = b0;
        for (; e + 4 <= e0; e += 4) {
            int s0 = __ldg(&d_csr[0][e + 0]);
            int s1 = __ldg(&d_csr[0][e + 1]);
            int s2 = __ldg(&d_csr[0][e + 2]);
            int s3 = __ldg(&d_csr[0][e + 3]);
            hf += __ldg(xin + (size_t)s0 * C + lane) + __ldg(xin + (size_t)s1 * C + lane)
                + __ldg(xin + (size_t)s2 * C + lane) + __ldg(xin + (size_t)s3 * C + lane);
        }
        for (; e < e0; e++)
            hf += __ldg(xin + (size_t)__ldg(&d_csr[0][e]) * C + lane);
        hf *= __ldg(&d_norm[0][node]);

        // backward: sum x over out-neighbors
        int b1 = __ldg(&d_off[1][node]), e1 = __ldg(&d_off[1][node + 1]);
        float hb = xv;
        e = b1;
        for (; e + 4 <= e1; e += 4) {
            int s0 = __ldg(&d_csr[1][e + 0]);
            int s1 = __ldg(&d_csr[1][e + 1]);
            int s2 = __ldg(&d_csr[1][e + 2]);
            int s3 = __ldg(&d_csr[1][e + 3]);
            hb += __ldg(xin + (size_t)s0 * C + lane) + __ldg(xin + (size_t)s1 * C + lane)
                + __ldg(xin + (size_t)s2 * C + lane) + __ldg(xin + (size_t)s3 * C + lane);
        }
        for (; e < e1; e++)
            hb += __ldg(xin + (size_t)__ldg(&d_csr[1][e]) * C + lane);
        hb *= __ldg(&d_norm[1][node]);

        shf[warp][lane] = hf;
        shb[warp][lane] = hb;
    }
    __syncwarp();

    if (node < n) {
        float a0 = 0.f, a1 = 0.f;
        #pragma unroll
        for (int k = 0; k < C; k++) {
            a0 = fmaf(shf[warp][k], sw[k * C + lane], a0);
            a1 = fmaf(shb[warp][k], sw[C * C + k * C + lane], a1);
        }
        xout[(size_t)node * C + lane] = xv + fmaxf(a0, 0.f) + fmaxf(a1, 0.f);
    }
}

// ---------------- pooling: per-graph sum + count (batch sorted) ----------------
__global__ void k_pool(const int* __restrict__ batch, const float* __restrict__ x, int n)
{
    int lane = threadIdx.x & 31;
    int warp = threadIdx.x >> 5;
    int base = blockIdx.x * 256 + warp * 32;

    float acc = 0.f;
    int cur = -1, run = 0;
    for (int j = 0; j < 32; j++) {
        int node = base + j;
        if (node >= n) break;
        int b = __ldg(batch + node);
        float v = __ldg(x + (size_t)node * C + lane);
        if (b != cur) {
            if (cur >= 0) {
                atomicAdd(&d_gsum[cur * C + lane], acc);
                if (lane == 0) atomicAdd(&d_gcnt[cur], (float)run);
            }
            cur = b; acc = 0.f; run = 0;
        }
        acc += v; run++;
    }
    if (cur >= 0) {
        atomicAdd(&d_gsum[cur * C + lane], acc);
        if (lane == 0) atomicAdd(&d_gcnt[cur], (float)run);
    }
}

// ---------------- MLP head ------------------------------------------------------
__global__ void k_mlp(const float* __restrict__ hw, const float* __restrict__ hb,
                      const float* __restrict__ ow, float* __restrict__ out)
{
    int b = blockIdx.x;
    __shared__ float gs[C];
    __shared__ float red[8];
    if (threadIdx.x < C)
        gs[threadIdx.x] = d_gsum[b * C + threadIdx.x] / d_gcnt[b];
    __syncthreads();

    float part = 0.f;
    for (int j = threadIdx.x; j < HIDDEN; j += 256) {
        float h = __ldg(hb + j);
        #pragma unroll
        for (int k = 0; k < C; k++)
            h = fmaf(gs[k], __ldg(hw + k * HIDDEN + j), h);
        part += fmaxf(h, 0.f) * __ldg(ow + j);
    }
    #pragma unroll
    for (int off = 16; off > 0; off >>= 1)
        part += __shfl_down_sync(0xffffffffu, part, off);
    if ((threadIdx.x & 31) == 0) red[threadIdx.x >> 5] = part;
    __syncthreads();
    if (threadIdx.x == 0) {
        float s = 0.f;
        #pragma unroll
        for (int i = 0; i < 8; i++) s += red[i];
        out[b] = s;
    }
}

// ---------------- launch ---------------------------------------------------------
extern "C" void kernel_launch(void* const* d_in, const int* in_sizes, int n_in,
                              void* d_out, int out_size)
{
    const int*   nodes    = (const int*)  d_in[0];
    const int*   sources  = (const int*)  d_in[1];
    const int*   targets  = (const int*)  d_in[2];
    const int*   batch    = (const int*)  d_in[3];
    const float* emb      = (const float*)d_in[4];
    const float* conv_w   = (const float*)d_in[5];
    const float* hidden_w = (const float*)d_in[6];
    const float* hidden_b = (const float*)d_in[7];
    const float* out_w    = (const float*)d_in[8];
    float*       out      = (float*)d_out;

    const int N = in_sizes[0];
    const int E = in_sizes[1];

    // CSR build (per call; graph-capturable, kernels only)
    k_zero   <<<(N_NODES + 255) / 256, 256>>>();
    k_hist   <<<(E + 255) / 256, 256>>>(sources, targets, E);
    k_scanA  <<<dim3(NBLK, 2), SCAN_BLK>>>();
    k_scanB  <<<dim3(1, 2),    SCAN_BLK>>>(E);
    k_scanC  <<<dim3(NBLK, 2), SCAN_BLK>>>();
    k_scatter<<<(E + 255) / 256, 256>>>(sources, targets, E);

    // init features
    {
        long long tot = (long long)N * C;
        k_init_x<<<(int)((tot + 255) / 256), 256>>>(nodes, emb, N);
    }

    // 8 fused layers, ping-pong buffers (even count -> final in d_xa)
    const int nb = (N + 7) / 8;
    float *xa = nullptr, *xb = nullptr;
    cudaGetSymbolAddress((void**)&xa, d_xa);
    cudaGetSymbolAddress((void**)&xb, d_xb);
    for (int l = 0; l < LAYERS; l++) {
        const float* wl = conv_w + (size_t)l * 2 * C * C;
        if ((l & 1) == 0) k_layer<<<nb, 256>>>(xa, xb, wl, N);
        else              k_layer<<<nb, 256>>>(xb, xa, wl, N);
    }
    k_pool<<<(N + 255) / 256, 256>>>(batch, xa, N);

    k_mlp<<<NGRAPH, 256>>>(hidden_w, hidden_b, out_w, out);
}